// round 15
// baseline (speedup 1.0000x reference)
#include <cuda_runtime.h>
#include <cuda_bf16.h>
#include <cuda_fp16.h>
#include <cstdint>
#include <math.h>

#define B_    2
#define S_    2048
#define D_    4096
#define H_    32
#define KVH_  8
#define HD_   128
#define HALF_ 64

// 1/sqrt(128) * log2(e): Q prescale so scores are in base-2 domain
#define SCALE_L2E 0.1275174455f

// ---------------------------------------------------------------------------
// Scratch (__device__ globals; allocation-free rule)
// ---------------------------------------------------------------------------
__device__ float g_v[(size_t)B_*S_*KVH_*HD_];
__device__ float g_vtile[(size_t)32*B_*KVH_*HD_];
__device__ float g_vsuf[(size_t)33*B_*KVH_*HD_];

__device__ __half g_xh[(size_t)B_*S_*D_];
__device__ __half g_xl[(size_t)B_*S_*D_];
__device__ __half g_wqT[(size_t)D_*H_*HD_];
__device__ __half g_wkT[(size_t)D_*KVH_*HD_];
__device__ __half g_wvT[(size_t)D_*KVH_*HD_];
__device__ __half g_woT[(size_t)D_*H_*HD_];
__device__ __half g_ah[(size_t)B_*S_*H_*HD_];

// Attention operands: Q fp16 hi/lo (prescaled), K single fp16, V fp16
__device__ __half g_qch[(size_t)B_*H_*S_*HD_];
__device__ __half g_qcl[(size_t)B_*H_*S_*HD_];
__device__ __half g_kch[(size_t)B_*KVH_*S_*HD_];
__device__ __half g_vt16[(size_t)B_*KVH_*HD_*S_];

// ---------------------------------------------------------------------------
// PTX helpers
// ---------------------------------------------------------------------------
__device__ __forceinline__ void mma16816h(float* c, const uint32_t* a,
                                          uint32_t b0, uint32_t b1) {
    asm volatile(
        "mma.sync.aligned.m16n8k16.row.col.f32.f16.f16.f32 "
        "{%0,%1,%2,%3}, {%4,%5,%6,%7}, {%8,%9}, {%0,%1,%2,%3};"
        : "+f"(c[0]), "+f"(c[1]), "+f"(c[2]), "+f"(c[3])
        : "r"(a[0]), "r"(a[1]), "r"(a[2]), "r"(a[3]), "r"(b0), "r"(b1));
}
#define LDSM4(R0, R1, R2, R3, ADDR) \
    asm volatile("ldmatrix.sync.aligned.m8n8.x4.shared.b16 {%0,%1,%2,%3}, [%4];" \
        : "=r"(R0), "=r"(R1), "=r"(R2), "=r"(R3) : "r"(ADDR))

__device__ __forceinline__ uint32_t smem_u32(const void* p) {
    uint32_t a;
    asm("{ .reg .u64 t; cvta.to.shared.u64 t, %1; cvt.u32.u64 %0, t; }"
        : "=r"(a) : "l"(p));
    return a;
}
#define CP16(dst, src) \
    asm volatile("cp.async.cg.shared.global [%0], [%1], 16;" \
        :: "r"(dst), "l"(src) : "memory")
#define CP_COMMIT() asm volatile("cp.async.commit_group;" ::: "memory")

__device__ __forceinline__ uint32_t pkh(float a, float b) {
    __half2 t = __floats2half2_rn(a, b);
    return *reinterpret_cast<uint32_t*>(&t);
}
__device__ __forceinline__ float ex2f(float a) {
    float d;
    asm("ex2.approx.f32 %0, %1;" : "=f"(d) : "f"(a));
    return d;
}
__device__ __forceinline__ void split_pair_h(float a, float b,
                                             uint32_t& hi, uint32_t& lo) {
    __half2 h2 = __floats2half2_rn(a, b);
    hi = *reinterpret_cast<uint32_t*>(&h2);
    __half2 l2 = __floats2half2_rn(a - __half2float(h2.x),
                                   b - __half2float(h2.y));
    lo = *reinterpret_cast<uint32_t*>(&l2);
}

// ---------------------------------------------------------------------------
// Conversion kernels
// ---------------------------------------------------------------------------
__global__ void split_conv_h(const float4* __restrict__ in,
                             __half* __restrict__ hi,
                             __half* __restrict__ lo, int n4) {
    int i = blockIdx.x * blockDim.x + threadIdx.x;
    if (i >= n4) return;
    float4 v = in[i];
    uint32_t h01, l01, h23, l23;
    split_pair_h(v.x, v.y, h01, l01);
    split_pair_h(v.z, v.w, h23, l23);
    uint2 hv = {h01, h23}, lv = {l01, l23};
    *(uint2*)(hi + i * 4) = hv;
    *(uint2*)(lo + i * 4) = lv;
}

// All four weight transposes in one launch: wq, wk, wv, wo.
__global__ void transp_all(const float* __restrict__ wq, const float* __restrict__ wk,
                           const float* __restrict__ wv, const float* __restrict__ wo,
                           __half* __restrict__ wqT, __half* __restrict__ wkT,
                           __half* __restrict__ wvT, __half* __restrict__ woT) {
    __shared__ float t[32][33];
    int bid = blockIdx.x;
    const float* in; __half* out; int R, C;
    if (bid < 16384)      { in = wq; out = wqT; R = 4096; C = 4096; }
    else if (bid < 20480) { bid -= 16384; in = wk; out = wkT; R = 4096; C = 1024; }
    else if (bid < 24576) { bid -= 20480; in = wv; out = wvT; R = 4096; C = 1024; }
    else                  { bid -= 24576; in = wo; out = woT; R = 4096; C = 4096; }
    int cb = bid % (C / 32), rb = bid / (C / 32);
    int c0 = cb * 32, r0 = rb * 32;
    int x = threadIdx.x, y = threadIdx.y;   // 32 x 8
#pragma unroll
    for (int j = 0; j < 32; j += 8)
        t[y + j][x] = in[(size_t)(r0 + y + j) * C + c0 + x];
    __syncthreads();
#pragma unroll
    for (int j = 0; j < 32; j += 8)
        out[(size_t)(c0 + y + j) * R + r0 + x] = __float2half(t[x][y + j]);
}

__global__ void conv_vt(const float* __restrict__ in, __half* __restrict__ o16) {
    __shared__ float t[32][33];
    int s0 = blockIdx.x * 32, d0 = blockIdx.y * 32;
    int kvh = blockIdx.z & 7, b = blockIdx.z >> 3;
    int x = threadIdx.x, y = threadIdx.y;
#pragma unroll
    for (int j = 0; j < 32; j += 8)
        t[y + j][x] = in[((size_t)(b * S_ + s0 + y + j) * KVH_ + kvh) * 128 + d0 + x];
    __syncthreads();
#pragma unroll
    for (int j = 0; j < 32; j += 8) {
        size_t o = ((size_t)(b * KVH_ + kvh) * 128 + d0 + y + j) * S_ + s0 + x;
        o16[o] = __float2half(t[x][y + j]);
    }
}

// ---------------------------------------------------------------------------
// Suffix-V
// ---------------------------------------------------------------------------
__global__ void vtile_sums(const float* __restrict__ V) {
    int d = threadIdx.x;
    int t = blockIdx.x;
    int kvh = blockIdx.y & 7, b = blockIdx.y >> 3;
    float acc = 0.f;
#pragma unroll 4
    for (int k = t * 64; k < t * 64 + 64; k++)
        acc += V[((size_t)(b * S_ + k) * KVH_ + kvh) * HD_ + d];
    g_vtile[((size_t)(t * B_ + b) * KVH_ + kvh) * HD_ + d] = acc;
}
__global__ void vsuffix_scan() {
    int idx = blockIdx.x * blockDim.x + threadIdx.x;
    int d = idx & 127, kvh = (idx >> 7) & 7, b = idx >> 10;
    float acc = 0.f;
    g_vsuf[((size_t)(32 * B_ + b) * KVH_ + kvh) * HD_ + d] = 0.f;
    for (int t = 31; t >= 0; t--) {
        acc += g_vtile[((size_t)(t * B_ + b) * KVH_ + kvh) * HD_ + d];
        g_vsuf[((size_t)(t * B_ + b) * KVH_ + kvh) * HD_ + d] = acc;
    }
}

// ---------------------------------------------------------------------------
// GEMM mainloop (runtime asplit): fp16, 128x128 tile, BK=64, 8 warps,
// cp.async 2-stage, ldmatrix. Fixed 3-region smem layout (A,Al,B).
// ---------------------------------------------------------------------------
#define STRG 72
#define GST3 (3 * 128 * STRG)           // halves per stage
#define GSMEM (2 * GST3 * 2)            // 110592 B -> occ 2

__device__ __forceinline__ void gemm_main_rt(
    const __half* __restrict__ Ah, const __half* __restrict__ Al,
    const __half* __restrict__ Bw, int asplit,
    int K, int m0, int n0, uint32_t sb, float acc[2][8][4])
{
    const int tid = threadIdx.x;
    const int lane = tid & 31, wid = tid >> 5;
    const int wm = (wid & 3) * 32, wn = (wid >> 2) * 64;
    const int NC = K / 64;

    const int lrow = tid >> 3, lcg = (tid & 7) * 8;   // 128 rows x 64 cols

    auto load_stage = [&](int s, int k0) {
        uint32_t sa = sb + (uint32_t)(s * GST3) * 2;
#pragma unroll
        for (int it = 0; it < 4; it++) {
            int row = lrow + it * 32;
            size_t ga = (size_t)(m0 + row) * K + k0 + lcg;
            size_t gb = (size_t)(n0 + row) * K + k0 + lcg;
            uint32_t o = (uint32_t)(row * STRG + lcg) * 2;
            CP16(sa + o, Ah + ga);
            if (asplit == 2) CP16(sa + 128*STRG*2 + o, Al + ga);
            CP16(sa + 2*128*STRG*2 + o, Bw + gb);
        }
        CP_COMMIT();
    };

    load_stage(0, 0);

    const int arow_in = lane & 15, acol_add = (lane >> 4) * 8;
    const int brow_in = (lane >> 4) * 8 + (lane & 7);
    const int bcol_add = ((lane >> 3) & 1) * 8;

    for (int i = 0; i < NC; i++) {
        if (i + 1 < NC) {
            load_stage((i + 1) & 1, (i + 1) * 64);
            asm volatile("cp.async.wait_group 1;" ::: "memory");
        } else {
            asm volatile("cp.async.wait_group 0;" ::: "memory");
        }
        __syncthreads();

        uint32_t sbase = sb + (uint32_t)((i & 1) * GST3) * 2;

#pragma unroll
        for (int kk2 = 0; kk2 < 4; kk2++) {
            const int kkc = kk2 * 16;
            uint32_t ah[2][4], al[2][4];
#pragma unroll
            for (int ii = 0; ii < 2; ii++) {
                uint32_t ao = (uint32_t)((wm + ii * 16 + arow_in) * STRG + kkc + acol_add) * 2;
                LDSM4(ah[ii][0], ah[ii][1], ah[ii][2], ah[ii][3], sbase + ao);
                if (asplit == 2)
                    LDSM4(al[ii][0], al[ii][1], al[ii][2], al[ii][3],
                          sbase + 128*STRG*2 + ao);
            }
            uint32_t bh[4][4];
#pragma unroll
            for (int jp = 0; jp < 4; jp++) {
                uint32_t bo = (uint32_t)((wn + jp * 16 + brow_in) * STRG + kkc + bcol_add) * 2;
                LDSM4(bh[jp][0], bh[jp][1], bh[jp][2], bh[jp][3],
                      sbase + 2*128*STRG*2 + bo);
            }
#pragma unroll
            for (int jp = 0; jp < 4; jp++) {
#pragma unroll
                for (int ii = 0; ii < 2; ii++) {
                    mma16816h(acc[ii][2*jp],   ah[ii], bh[jp][0], bh[jp][1]);
                    mma16816h(acc[ii][2*jp+1], ah[ii], bh[jp][2], bh[jp][3]);
                }
            }
            if (asplit == 2) {
#pragma unroll
                for (int jp = 0; jp < 4; jp++) {
#pragma unroll
                    for (int ii = 0; ii < 2; ii++) {
                        mma16816h(acc[ii][2*jp],   al[ii], bh[jp][0], bh[jp][1]);
                        mma16816h(acc[ii][2*jp+1], al[ii], bh[jp][2], bh[jp][3]);
                    }
                }
            }
        }
        __syncthreads();
    }
}

// ---------------------------------------------------------------------------
// Fused QKV projection: blockIdx.x selects mode (Q / K / V), epilogue varies.
//   mode 0 (gx  0..31): Q = x@wq, RoPE, prescale, fp16 hi/lo out, asplit 1
//   mode 1 (gx 32..39): K = x@wk, RoPE, fp16 out, asplit 2
//   mode 2 (gx 40..47): V = x@wv, fp32 out, asplit 1
// ---------------------------------------------------------------------------
__global__ void __launch_bounds__(256, 2)
qkv_fused(const __half* __restrict__ xh, const __half* __restrict__ xl,
          const __half* __restrict__ wqT, const __half* __restrict__ wkT,
          const __half* __restrict__ wvT,
          __half* __restrict__ qch, __half* __restrict__ qcl,
          __half* __restrict__ kch, float* __restrict__ vb,
          const float* __restrict__ fcos, const float* __restrict__ fsin) {
    extern __shared__ __half dsm[];
    const uint32_t sb = smem_u32(dsm);
    const int lane = threadIdx.x & 31, wid = threadIdx.x >> 5;
    const int wm = (wid & 3) * 32, wn = (wid >> 2) * 64;
    const int m0 = blockIdx.y * 128;
    const int gx = blockIdx.x;

    int mode, n0, asplit;
    const __half* Bw;
    if (gx < 32)      { mode = 0; n0 = gx * 128;        Bw = wqT; asplit = 1; }
    else if (gx < 40) { mode = 1; n0 = (gx - 32) * 128; Bw = wkT; asplit = 2; }
    else              { mode = 2; n0 = (gx - 40) * 128; Bw = wvT; asplit = 1; }

    float acc[2][8][4];
#pragma unroll
    for (int i = 0; i < 2; i++)
#pragma unroll
        for (int j = 0; j < 8; j++)
#pragma unroll
            for (int v = 0; v < 4; v++) acc[i][j][v] = 0.f;

    gemm_main_rt(xh, xl, Bw, asplit, D_, m0, n0, sb, acc);

    const int fr = lane >> 2, fc = (lane & 3) * 2;
    if (mode == 2) {
        // V: plain fp32 epilogue, N = 1024
#pragma unroll
        for (int i = 0; i < 2; i++) {
#pragma unroll
            for (int j = 0; j < 8; j++) {
                int row = m0 + wm + i * 16 + fr;
                int col = n0 + wn + j * 8 + fc;
                float2 v0 = {acc[i][j][0], acc[i][j][1]};
                float2 v1 = {acc[i][j][2], acc[i][j][3]};
                *(float2*)&vb[(size_t)row * 1024 + col] = v0;
                *(float2*)&vb[(size_t)(row + 8) * 1024 + col] = v1;
            }
        }
        return;
    }

    // Q / K: fused RoPE + head-permute epilogue
    const int heads = (mode == 0) ? H_ : KVH_;
    const float prescale = (mode == 0) ? SCALE_L2E : 1.0f;
    const int do_split = (mode == 0);
    __half* Ohi = (mode == 0) ? qch : kch;
    __half* Olo = qcl;
#pragma unroll
    for (int i = 0; i < 2; i++) {
#pragma unroll
        for (int j = 0; j < 8; j++) {
            int col = n0 + wn + j * 8 + fc;      // even
            int hh = col >> 7, d = col & 127, ip = d >> 1;
#pragma unroll
            for (int rsel = 0; rsel < 2; rsel++) {
                int r = m0 + wm + i * 16 + fr + rsel * 8;
                int s = r & (S_ - 1), bb = r >> 11;
                float c = fcos[s * 64 + ip], sn = fsin[s * 64 + ip];
                float a = acc[i][j][rsel * 2 + 0];
                float b2 = acc[i][j][rsel * 2 + 1];
                float ra = (a * c - b2 * sn) * prescale;
                float rb = (a * sn + b2 * c) * prescale;
                size_t o = (((size_t)(bb * heads + hh) * S_) + s) * 128 + d;
                __half2 h2 = __floats2half2_rn(ra, rb);
                *(uint32_t*)(Ohi + o) = *reinterpret_cast<uint32_t*>(&h2);
                if (do_split) {
                    __half2 l2 = __floats2half2_rn(ra - __half2float(h2.x),
                                                   rb - __half2float(h2.y));
                    *(uint32_t*)(Olo + o) = *reinterpret_cast<uint32_t*>(&l2);
                }
            }
        }
    }
}

// O-projection: single-A fp16, fp32 out (separate launch; depends on attention)
__global__ void __launch_bounds__(256, 2)
gemm_oproj(const __half* __restrict__ Ah, const __half* __restrict__ Bw,
           float* __restrict__ C, int M, int N, int K) {
    extern __shared__ __half dsm[];
    const uint32_t sb = smem_u32(dsm);
    const int lane = threadIdx.x & 31, wid = threadIdx.x >> 5;
    const int wm = (wid & 3) * 32, wn = (wid >> 2) * 64;
    const int m0 = blockIdx.y * 128, n0 = blockIdx.x * 128;

    float acc[2][8][4];
#pragma unroll
    for (int i = 0; i < 2; i++)
#pragma unroll
        for (int j = 0; j < 8; j++)
#pragma unroll
            for (int v = 0; v < 4; v++) acc[i][j][v] = 0.f;

    gemm_main_rt(Ah, Ah, Bw, 1, K, m0, n0, sb, acc);

    const int fr = lane >> 2, fc = (lane & 3) * 2;
#pragma unroll
    for (int i = 0; i < 2; i++) {
#pragma unroll
        for (int j = 0; j < 8; j++) {
            int row = m0 + wm + i * 16 + fr;
            int col = n0 + wn + j * 8 + fc;
            float2 v0 = {acc[i][j][0], acc[i][j][1]};
            float2 v1 = {acc[i][j][2], acc[i][j][3]};
            *(float2*)&C[(size_t)row * N + col] = v0;
            *(float2*)&C[(size_t)(row + 8) * N + col] = v1;
        }
    }
}

// ---------------------------------------------------------------------------
// HMMA flash attention (best-measured shape): 256 threads / 128 q-rows,
// base-2 scores (Q prescaled), fp32 ex2 softmax, l via ones-MMA,
// conditional rescale, per-warp mask skip, cp.async 2-stage K/V, fp16 out.
// ---------------------------------------------------------------------------
#define QSTRD 136
#define VSTRD 72
#define KV_STG_H (64 * QSTRD + 128 * VSTRD)
#define ATTN_SMEM ((2 * 128 * QSTRD + 2 * KV_STG_H) * 2)

__global__ void __launch_bounds__(256, 1)
attn_hmma(const __half* __restrict__ Qh, const __half* __restrict__ Ql,
          const __half* __restrict__ Kh, const __half* __restrict__ Vt16,
          __half* __restrict__ O16) {
    extern __shared__ __half hsm[];
    __half* sQh = hsm;
    __half* sQl = sQh + 128 * QSTRD;
    __half* kvs = sQl + 128 * QSTRD;

    const uint32_t sQh_a = smem_u32(sQh);
    const uint32_t sQl_a = smem_u32(sQl);
    const uint32_t kv_a  = smem_u32(kvs);

    const int tid = threadIdx.x;
    const int lane = tid & 31, wid = tid >> 5;
    const int h  = blockIdx.x;
    const int bx = (gridDim.y - 1) - blockIdx.y;   // heavy tiles first
    const int b  = blockIdx.z;
    const int q0 = bx * 128;
    const int kvh = h >> 2;
    const int fr = lane >> 2, fc2 = (lane & 3) * 2;
    const int wr0 = wid * 16;

    {
        const size_t qg = (((size_t)(b * H_ + h) * S_) + q0) * 128;
#pragma unroll
        for (int it = 0; it < 8; it++) {
            int idx = tid + it * 256;
            int row = idx >> 4, c8 = (idx & 15) * 8;
            *(uint4*)&sQh[row * QSTRD + c8] = *(const uint4*)(Qh + qg + (size_t)row * 128 + c8);
            *(uint4*)&sQl[row * QSTRD + c8] = *(const uint4*)(Ql + qg + (size_t)row * 128 + c8);
        }
    }

    const size_t kgb = ((size_t)(b * KVH_ + kvh) * S_) * 128;
    const size_t vgb = ((size_t)(b * KVH_ + kvh) * 128) * S_;

    auto load_kv = [&](int kt, int stg) {
        uint32_t sa = kv_a + (uint32_t)(stg * KV_STG_H) * 2;
        const int k0 = kt * 64;
#pragma unroll
        for (int it = 0; it < 4; it++) {
            int idx = tid + it * 256;
            int row = idx >> 4, c8 = (idx & 15) * 8;
            CP16(sa + (uint32_t)(row * QSTRD + c8) * 2,
                 Kh + kgb + (size_t)(k0 + row) * 128 + c8);
        }
#pragma unroll
        for (int it = 0; it < 4; it++) {
            int idx = tid + it * 256;
            int row = idx >> 3, c8 = (idx & 7) * 8;
            CP16(sa + 64*QSTRD*2 + (uint32_t)(row * VSTRD + c8) * 2,
                 Vt16 + vgb + (size_t)row * S_ + k0 + c8);
        }
        CP_COMMIT();
    };

    float o_acc[16][4];
#pragma unroll
    for (int j = 0; j < 16; j++)
#pragma unroll
        for (int c = 0; c < 4; c++) o_acc[j][c] = 0.f;
    float l_acc[4] = {0.f, 0.f, 0.f, 0.f};
    float m0 = -1e30f, m1 = -1e30f;

    const int ntiles = 2 * bx + 2;
    const int r0g = q0 + wr0 + fr, r1g = r0g + 8;

    const int arow_in = lane & 15, acol_add = (lane >> 4) * 8;
    const int brow_in = (lane >> 4) * 8 + (lane & 7);
    const int bcol_add = ((lane >> 3) & 1) * 8;
    const uint32_t ONES = 0x3C003C00u;

    load_kv(0, 0);
    __syncthreads();

    for (int kt = 0; kt < ntiles; kt++) {
        const int k0 = kt * 64;
        const int stg = kt & 1;
        if (kt + 1 < ntiles) {
            load_kv(kt + 1, stg ^ 1);
            asm volatile("cp.async.wait_group 1;" ::: "memory");
        } else {
            asm volatile("cp.async.wait_group 0;" ::: "memory");
        }
        __syncthreads();

        const uint32_t sK_a = kv_a + (uint32_t)(stg * KV_STG_H) * 2;
        const uint32_t sV_a = sK_a + 64*QSTRD*2;

        // ---- QK^T (base-2 domain) ----
        float s[8][4];
#pragma unroll
        for (int j = 0; j < 8; j++)
#pragma unroll
            for (int c = 0; c < 4; c++) s[j][c] = 0.f;

#pragma unroll
        for (int kk = 0; kk < 8; kk++) {
            const int kkc = kk * 16;
            uint32_t ah[4], al[4];
            uint32_t ao = (uint32_t)((wr0 + arow_in) * QSTRD + kkc + acol_add) * 2;
            LDSM4(ah[0], ah[1], ah[2], ah[3], sQh_a + ao);
            LDSM4(al[0], al[1], al[2], al[3], sQl_a + ao);
#pragma unroll
            for (int jp = 0; jp < 4; jp++) {
                uint32_t bo = (uint32_t)((jp * 16 + brow_in) * QSTRD + kkc + bcol_add) * 2;
                uint32_t bh[4];
                LDSM4(bh[0], bh[1], bh[2], bh[3], sK_a + bo);
                mma16816h(s[2*jp],   ah, bh[0], bh[1]);
                mma16816h(s[2*jp],   al, bh[0], bh[1]);
                mma16816h(s[2*jp+1], ah, bh[2], bh[3]);
                mma16816h(s[2*jp+1], al, bh[2], bh[3]);
            }
        }

        // ---- mask (skip fully-causal tiles for this warp) ----
        if (k0 + 63 > q0 + wr0) {
#pragma unroll
            for (int j = 0; j < 8; j++) {
                int c0g = k0 + j * 8 + fc2, c1g = c0g + 1;
                s[j][0] = (c0g <= r0g) ? s[j][0] : 0.f;
                s[j][1] = (c1g <= r0g) ? s[j][1] : 0.f;
                s[j][2] = (c0g <= r1g) ? s[j][2] : 0.f;
                s[j][3] = (c1g <= r1g) ? s[j][3] : 0.f;
            }
        }

        // ---- row max ----
        float rm0 = -1e30f, rm1 = -1e30f;
#pragma unroll
        for (int j = 0; j < 8; j++) {
            rm0 = fmaxf(rm0, fmaxf(s[j][0], s[j][1]));
            rm1 = fmaxf(rm1, fmaxf(s[j][2], s[j][3]));
        }
        rm0 = fmaxf(rm0, __shfl_xor_sync(0xffffffffu, rm0, 1));
        rm0 = fmaxf(rm0, __shfl_xor_sync(0xffffffffu, rm0, 2));
        rm1 = fmaxf(rm1, __shfl_xor_sync(0xffffffffu, rm1, 1));
        rm1 = fmaxf(rm1, __shfl_xor_sync(0xffffffffu, rm1, 2));

        float mn0 = fmaxf(m0, rm0), mn1 = fmaxf(m1, rm1);
        if (mn0 > m0 || mn1 > m1) {
            float f0 = ex2f(m0 - mn0), f1 = ex2f(m1 - mn1);
#pragma unroll
            for (int j = 0; j < 16; j++) {
                o_acc[j][0] *= f0; o_acc[j][1] *= f0;
                o_acc[j][2] *= f1; o_acc[j][3] *= f1;
            }
            l_acc[0] *= f0; l_acc[1] *= f0;
            l_acc[2] *= f1; l_acc[3] *= f1;
            m0 = mn0; m1 = mn1;
        }

        // ---- P = exp2(s - m), fp32 ex2 then pack ----
        uint32_t P0[8], P1[8];
#pragma unroll
        for (int j = 0; j < 8; j++) {
            P0[j] = pkh(ex2f(s[j][0] - m0), ex2f(s[j][1] - m0));
            P1[j] = pkh(ex2f(s[j][2] - m1), ex2f(s[j][3] - m1));
        }

        // ---- P @ V + l (ones-column MMA) ----
#pragma unroll
        for (int kk2 = 0; kk2 < 4; kk2++) {
            uint32_t ph[4] = {P0[2*kk2], P1[2*kk2], P0[2*kk2+1], P1[2*kk2+1]};
            mma16816h(l_acc, ph, ONES, ONES);
#pragma unroll
            for (int jp2 = 0; jp2 < 8; jp2++) {
                uint32_t vo = (uint32_t)((jp2 * 16 + brow_in) * VSTRD + kk2 * 16 + bcol_add) * 2;
                uint32_t vh[4];
                LDSM4(vh[0], vh[1], vh[2], vh[3], sV_a + vo);
                mma16816h(o_acc[2*jp2],   ph, vh[0], vh[1]);
                mma16816h(o_acc[2*jp2+1], ph, vh[2], vh[3]);
            }
        }
        __syncthreads();
    }

    float l0 = l_acc[0], l1 = l_acc[2];

    // ---- analytic masked tail ----
    const int n_tail = S_ - (q0 + 128);
    if (n_tail > 0) {
        const float* suf = g_vsuf + ((size_t)(ntiles * B_ + b) * KVH_ + kvh) * HD_;
        float mn0 = fmaxf(m0, 0.f), mn1 = fmaxf(m1, 0.f);
        float f0 = ex2f(m0 - mn0), f1 = ex2f(m1 - mn1);
        float pt0 = ex2f(0.f - mn0), pt1 = ex2f(0.f - mn1);
        l0 = l0 * f0 + (float)n_tail * pt0;
        l1 = l1 * f1 + (float)n_tail * pt1;
#pragma unroll
        for (int j2 = 0; j2 < 16; j2++) {
            float2 sv = *(const float2*)(suf + j2 * 8 + fc2);
            o_acc[j2][0] = o_acc[j2][0] * f0 + pt0 * sv.x;
            o_acc[j2][1] = o_acc[j2][1] * f0 + pt0 * sv.y;
            o_acc[j2][2] = o_acc[j2][2] * f1 + pt1 * sv.x;
            o_acc[j2][3] = o_acc[j2][3] * f1 + pt1 * sv.y;
        }
    }

    // ---- normalize + write fp16 [b, s, h*128 + d] ----
    const float inv0 = 1.f / l0, inv1 = 1.f / l1;
    const size_t ob0 = (size_t)(b * S_ + r0g) * (H_ * HD_) + h * HD_;
    const size_t ob1 = (size_t)(b * S_ + r1g) * (H_ * HD_) + h * HD_;
#pragma unroll
    for (int j2 = 0; j2 < 16; j2++) {
        int d = j2 * 8 + fc2;
        *(uint32_t*)(O16 + ob0 + d) = pkh(o_acc[j2][0] * inv0, o_acc[j2][1] * inv0);
        *(uint32_t*)(O16 + ob1 + d) = pkh(o_acc[j2][2] * inv1, o_acc[j2][3] * inv1);
    }
}

// ---------------------------------------------------------------------------
// Inputs: 0:x 1:freqs_cos 2:freqs_sin 3:mask 4:wq 5:wk 6:wv 7:wo
//         8:cache_k 9:cache_v 10:start_pos
// ---------------------------------------------------------------------------
extern "C" void kernel_launch(void* const* d_in, const int* in_sizes, int n_in,
                              void* d_out, int out_size) {
    const float* x    = (const float*)d_in[0];
    const float* fcos = (const float*)d_in[1];
    const float* fsin = (const float*)d_in[2];
    const float* wq   = (const float*)d_in[4];
    const float* wk   = (const float*)d_in[5];
    const float* wv   = (const float*)d_in[6];
    const float* wo   = (const float*)d_in[7];
    float* out = (float*)d_out;

    float* vb;
    cudaGetSymbolAddress((void**)&vb, g_v);
    __half *xh, *xl, *wqT, *wkT, *wvT, *woT, *ah;
    __half *qch, *qcl, *kch, *vt16;
    cudaGetSymbolAddress((void**)&xh,  g_xh);
    cudaGetSymbolAddress((void**)&xl,  g_xl);
    cudaGetSymbolAddress((void**)&wqT, g_wqT);
    cudaGetSymbolAddress((void**)&wkT, g_wkT);
    cudaGetSymbolAddress((void**)&wvT, g_wvT);
    cudaGetSymbolAddress((void**)&woT, g_woT);
    cudaGetSymbolAddress((void**)&ah,  g_ah);
    cudaGetSymbolAddress((void**)&qch, g_qch);
    cudaGetSymbolAddress((void**)&qcl, g_qcl);
    cudaGetSymbolAddress((void**)&kch, g_kch);
    cudaGetSymbolAddress((void**)&vt16, g_vt16);

    const int M = B_ * S_;

    cudaFuncSetAttribute(qkv_fused, cudaFuncAttributeMaxDynamicSharedMemorySize,
                         GSMEM);
    cudaFuncSetAttribute(gemm_oproj, cudaFuncAttributeMaxDynamicSharedMemorySize,
                         GSMEM);
    cudaFuncSetAttribute(attn_hmma, cudaFuncAttributeMaxDynamicSharedMemorySize,
                         ATTN_SMEM);

    // 1: activation split
    {
        int n4 = M * D_ / 4;
        split_conv_h<<<(n4 + 255) / 256, 256>>>((const float4*)x, xh, xl, n4);
    }
    // 2: all weight transposes in one launch
    transp_all<<<40960, dim3(32, 8)>>>(wq, wk, wv, wo, wqT, wkT, wvT, woT);

    // 3: fused QKV projection
    qkv_fused<<<dim3(48, M / 128), 256, GSMEM>>>(
        xh, xl, wqT, wkT, wvT, qch, qcl, kch, vb, fcos, fsin);

    // 4-5: suffix V sums
    vtile_sums<<<dim3(32, B_ * KVH_), 128>>>(vb);
    vsuffix_scan<<<8, 256>>>();

    // 6: V transpose to fp16
    conv_vt<<<dim3(S_ / 32, HD_ / 32, B_ * KVH_), dim3(32, 8)>>>(vb, vt16);

    // 7: attention
    attn_hmma<<<dim3(H_, S_ / 128, B_), 256, ATTN_SMEM>>>(qch, qcl, kch, vt16, ah);

    // 8: output projection
    gemm_oproj<<<dim3(D_ / 128, M / 128), 256, GSMEM>>>(ah, woT, out, M, D_, D_);
}

// round 16
// speedup vs baseline: 1.0087x; 1.0087x over previous
#include <cuda_runtime.h>
#include <cuda_bf16.h>
#include <cuda_fp16.h>
#include <cstdint>
#include <math.h>

#define B_    2
#define S_    2048
#define D_    4096
#define H_    32
#define KVH_  8
#define HD_   128
#define HALF_ 64

// 1/sqrt(128) * log2(e): Q prescale so scores are in base-2 domain
#define SCALE_L2E 0.1275174455f

// ---------------------------------------------------------------------------
// Scratch (__device__ globals; allocation-free rule)
// ---------------------------------------------------------------------------
__device__ float g_vtile[(size_t)32*B_*KVH_*HD_];
__device__ float g_vsuf[(size_t)33*B_*KVH_*HD_];

__device__ __half g_xh[(size_t)B_*S_*D_];
__device__ __half g_xl[(size_t)B_*S_*D_];
__device__ __half g_wqT[(size_t)D_*H_*HD_];
__device__ __half g_wkT[(size_t)D_*KVH_*HD_];
__device__ __half g_wvT[(size_t)D_*KVH_*HD_];
__device__ __half g_woT[(size_t)D_*H_*HD_];
__device__ __half g_ah[(size_t)B_*S_*H_*HD_];

// Attention operands: Q fp16 hi/lo (prescaled), K single fp16, V fp16
__device__ __half g_qch[(size_t)B_*H_*S_*HD_];
__device__ __half g_qcl[(size_t)B_*H_*S_*HD_];
__device__ __half g_kch[(size_t)B_*KVH_*S_*HD_];
__device__ __half g_vt16[(size_t)B_*KVH_*HD_*S_];   // [b,kvh,d,s]

// ---------------------------------------------------------------------------
// PTX helpers
// ---------------------------------------------------------------------------
__device__ __forceinline__ void mma16816h(float* c, const uint32_t* a,
                                          uint32_t b0, uint32_t b1) {
    asm volatile(
        "mma.sync.aligned.m16n8k16.row.col.f32.f16.f16.f32 "
        "{%0,%1,%2,%3}, {%4,%5,%6,%7}, {%8,%9}, {%0,%1,%2,%3};"
        : "+f"(c[0]), "+f"(c[1]), "+f"(c[2]), "+f"(c[3])
        : "r"(a[0]), "r"(a[1]), "r"(a[2]), "r"(a[3]), "r"(b0), "r"(b1));
}
#define LDSM4(R0, R1, R2, R3, ADDR) \
    asm volatile("ldmatrix.sync.aligned.m8n8.x4.shared.b16 {%0,%1,%2,%3}, [%4];" \
        : "=r"(R0), "=r"(R1), "=r"(R2), "=r"(R3) : "r"(ADDR))

__device__ __forceinline__ uint32_t smem_u32(const void* p) {
    uint32_t a;
    asm("{ .reg .u64 t; cvta.to.shared.u64 t, %1; cvt.u32.u64 %0, t; }"
        : "=r"(a) : "l"(p));
    return a;
}
#define CP16(dst, src) \
    asm volatile("cp.async.cg.shared.global [%0], [%1], 16;" \
        :: "r"(dst), "l"(src) : "memory")
#define CP_COMMIT() asm volatile("cp.async.commit_group;" ::: "memory")

__device__ __forceinline__ uint32_t pkh(float a, float b) {
    __half2 t = __floats2half2_rn(a, b);
    return *reinterpret_cast<uint32_t*>(&t);
}
__device__ __forceinline__ float ex2f(float a) {
    float d;
    asm("ex2.approx.f32 %0, %1;" : "=f"(d) : "f"(a));
    return d;
}
__device__ __forceinline__ void split_pair_h(float a, float b,
                                             uint32_t& hi, uint32_t& lo) {
    __half2 h2 = __floats2half2_rn(a, b);
    hi = *reinterpret_cast<uint32_t*>(&h2);
    __half2 l2 = __floats2half2_rn(a - __half2float(h2.x),
                                   b - __half2float(h2.y));
    lo = *reinterpret_cast<uint32_t*>(&l2);
}

// ---------------------------------------------------------------------------
// Conversion kernels
// ---------------------------------------------------------------------------
__global__ void split_conv_h(const float4* __restrict__ in,
                             __half* __restrict__ hi,
                             __half* __restrict__ lo, int n4) {
    int i = blockIdx.x * blockDim.x + threadIdx.x;
    if (i >= n4) return;
    float4 v = in[i];
    uint32_t h01, l01, h23, l23;
    split_pair_h(v.x, v.y, h01, l01);
    split_pair_h(v.z, v.w, h23, l23);
    uint2 hv = {h01, h23}, lv = {l01, l23};
    *(uint2*)(hi + i * 4) = hv;
    *(uint2*)(lo + i * 4) = lv;
}

// All four weight transposes in one launch: wq, wk, wv, wo.
__global__ void transp_all(const float* __restrict__ wq, const float* __restrict__ wk,
                           const float* __restrict__ wv, const float* __restrict__ wo,
                           __half* __restrict__ wqT, __half* __restrict__ wkT,
                           __half* __restrict__ wvT, __half* __restrict__ woT) {
    __shared__ float t[32][33];
    int bid = blockIdx.x;
    const float* in; __half* out; int R, C;
    if (bid < 16384)      { in = wq; out = wqT; R = 4096; C = 4096; }
    else if (bid < 20480) { bid -= 16384; in = wk; out = wkT; R = 4096; C = 1024; }
    else if (bid < 24576) { bid -= 20480; in = wv; out = wvT; R = 4096; C = 1024; }
    else                  { bid -= 24576; in = wo; out = woT; R = 4096; C = 4096; }
    int cb = bid % (C / 32), rb = bid / (C / 32);
    int c0 = cb * 32, r0 = rb * 32;
    int x = threadIdx.x, y = threadIdx.y;   // 32 x 8
#pragma unroll
    for (int j = 0; j < 32; j += 8)
        t[y + j][x] = in[(size_t)(r0 + y + j) * C + c0 + x];
    __syncthreads();
#pragma unroll
    for (int j = 0; j < 32; j += 8)
        out[(size_t)(c0 + y + j) * R + r0 + x] = __float2half(t[x][y + j]);
}

// ---------------------------------------------------------------------------
// Suffix-V from fp16 transposed V: [b,kvh,d,s]
// ---------------------------------------------------------------------------
__global__ void vtile_sums(const __half* __restrict__ V16) {
    int d = threadIdx.x;                 // 0..127
    int t = blockIdx.x;                  // 0..31
    int kvh = blockIdx.y & 7, b = blockIdx.y >> 3;
    const __half* p = V16 + ((size_t)((b * KVH_ + kvh) * 128 + d)) * S_ + t * 64;
    float acc = 0.f;
#pragma unroll 8
    for (int k = 0; k < 64; k++)
        acc += __half2float(p[k]);
    g_vtile[((size_t)(t * B_ + b) * KVH_ + kvh) * HD_ + d] = acc;
}
__global__ void vsuffix_scan() {
    int idx = blockIdx.x * blockDim.x + threadIdx.x;
    int d = idx & 127, kvh = (idx >> 7) & 7, b = idx >> 10;
    float acc = 0.f;
    g_vsuf[((size_t)(32 * B_ + b) * KVH_ + kvh) * HD_ + d] = 0.f;
    for (int t = 31; t >= 0; t--) {
        acc += g_vtile[((size_t)(t * B_ + b) * KVH_ + kvh) * HD_ + d];
        g_vsuf[((size_t)(t * B_ + b) * KVH_ + kvh) * HD_ + d] = acc;
    }
}

// ---------------------------------------------------------------------------
// GEMM mainloop: fp16, A-split x ASPLIT, 128x128 tile, BK=64, 8 warps,
// cp.async 2-stage, ldmatrix. C = A[M,K] @ B[N,K]^T.
// ---------------------------------------------------------------------------
#define STRG 72
#define GSMEM_1 (2 * (2 * 128 * STRG) * 2)   // 73728 B
#define GSMEM_2 (2 * (3 * 128 * STRG) * 2)   // 110592 B

template <int ASPLIT>
__device__ __forceinline__ void gemm_main(
    const __half* __restrict__ Ah, const __half* __restrict__ Al,
    const __half* __restrict__ Bw,
    int K, int m0, int n0, uint32_t sb, float acc[2][8][4])
{
    const int tid = threadIdx.x;
    const int lane = tid & 31, wid = tid >> 5;
    const int wm = (wid & 3) * 32, wn = (wid >> 2) * 64;
    const uint32_t GST = (uint32_t)((1 + ASPLIT) * 128 * STRG);
    const int NC = K / 64;

    const int lrow = tid >> 3, lcg = (tid & 7) * 8;   // 128 rows x 64 cols

    auto load_stage = [&](int s, int k0) {
        uint32_t sa = sb + (uint32_t)s * GST * 2;
#pragma unroll
        for (int it = 0; it < 4; it++) {
            int row = lrow + it * 32;
            size_t ga = (size_t)(m0 + row) * K + k0 + lcg;
            size_t gb = (size_t)(n0 + row) * K + k0 + lcg;
            uint32_t o = (uint32_t)(row * STRG + lcg) * 2;
            CP16(sa + o, Ah + ga);
            if (ASPLIT == 2) CP16(sa + 128*STRG*2 + o, Al + ga);
            CP16(sa + (uint32_t)(ASPLIT * 128 * STRG) * 2 + o, Bw + gb);
        }
        CP_COMMIT();
    };

    load_stage(0, 0);

    const int arow_in = lane & 15, acol_add = (lane >> 4) * 8;
    const int brow_in = (lane >> 4) * 8 + (lane & 7);
    const int bcol_add = ((lane >> 3) & 1) * 8;

    for (int i = 0; i < NC; i++) {
        if (i + 1 < NC) {
            load_stage((i + 1) & 1, (i + 1) * 64);
            asm volatile("cp.async.wait_group 1;" ::: "memory");
        } else {
            asm volatile("cp.async.wait_group 0;" ::: "memory");
        }
        __syncthreads();

        uint32_t sbase = sb + (uint32_t)((i & 1) * GST) * 2;

#pragma unroll
        for (int kk2 = 0; kk2 < 4; kk2++) {
            const int kkc = kk2 * 16;
            uint32_t ah[2][4], al[2][4];
#pragma unroll
            for (int ii = 0; ii < 2; ii++) {
                uint32_t ao = (uint32_t)((wm + ii * 16 + arow_in) * STRG + kkc + acol_add) * 2;
                LDSM4(ah[ii][0], ah[ii][1], ah[ii][2], ah[ii][3], sbase + ao);
                if (ASPLIT == 2)
                    LDSM4(al[ii][0], al[ii][1], al[ii][2], al[ii][3],
                          sbase + 128*STRG*2 + ao);
            }
            uint32_t bh[4][4];
#pragma unroll
            for (int jp = 0; jp < 4; jp++) {
                uint32_t bo = (uint32_t)((wn + jp * 16 + brow_in) * STRG + kkc + bcol_add) * 2;
                LDSM4(bh[jp][0], bh[jp][1], bh[jp][2], bh[jp][3],
                      sbase + (uint32_t)(ASPLIT * 128 * STRG) * 2 + bo);
            }
#pragma unroll
            for (int jp = 0; jp < 4; jp++) {
#pragma unroll
                for (int ii = 0; ii < 2; ii++) {
                    mma16816h(acc[ii][2*jp],   ah[ii], bh[jp][0], bh[jp][1]);
                    if (ASPLIT == 2)
                        mma16816h(acc[ii][2*jp], al[ii], bh[jp][0], bh[jp][1]);
                    mma16816h(acc[ii][2*jp+1], ah[ii], bh[jp][2], bh[jp][3]);
                    if (ASPLIT == 2)
                        mma16816h(acc[ii][2*jp+1], al[ii], bh[jp][2], bh[jp][3]);
                }
            }
        }
        __syncthreads();
    }
}

// Plain fp32 epilogue (O projection)
template <int ASPLIT>
__global__ void __launch_bounds__(256, 2)
gemm_hmma(const __half* __restrict__ Ah, const __half* __restrict__ Al,
          const __half* __restrict__ Bw,
          float* __restrict__ C, int M, int N, int K) {
    extern __shared__ __half dsm[];
    const uint32_t sb = smem_u32(dsm);
    const int lane = threadIdx.x & 31, wid = threadIdx.x >> 5;
    const int wm = (wid & 3) * 32, wn = (wid >> 2) * 64;
    const int m0 = blockIdx.y * 128, n0 = blockIdx.x * 128;

    float acc[2][8][4];
#pragma unroll
    for (int i = 0; i < 2; i++)
#pragma unroll
        for (int j = 0; j < 8; j++)
#pragma unroll
            for (int v = 0; v < 4; v++) acc[i][j][v] = 0.f;

    gemm_main<ASPLIT>(Ah, Al, Bw, K, m0, n0, sb, acc);

    const int fr = lane >> 2, fc = (lane & 3) * 2;
#pragma unroll
    for (int i = 0; i < 2; i++) {
#pragma unroll
        for (int j = 0; j < 8; j++) {
            int row = m0 + wm + i * 16 + fr;
            int col = n0 + wn + j * 8 + fc;
            float2 v0 = {acc[i][j][0], acc[i][j][1]};
            float2 v1 = {acc[i][j][2], acc[i][j][3]};
            *(float2*)&C[(size_t)row * N + col] = v0;
            *(float2*)&C[(size_t)(row + 8) * N + col] = v1;
        }
    }
}

// V projection: single-A fp16 mainloop, epilogue writes TRANSPOSED fp16
// directly into g_vt16 layout [b,kvh,d,s]  (eliminates fp32 V + conv_vt).
__global__ void __launch_bounds__(256, 2)
gemm_vproj(const __half* __restrict__ Ah, const __half* __restrict__ Bw,
           __half* __restrict__ Vt) {
    extern __shared__ __half dsm[];
    const uint32_t sb = smem_u32(dsm);
    const int lane = threadIdx.x & 31, wid = threadIdx.x >> 5;
    const int wm = (wid & 3) * 32, wn = (wid >> 2) * 64;
    const int m0 = blockIdx.y * 128, n0 = blockIdx.x * 128;

    float acc[2][8][4];
#pragma unroll
    for (int i = 0; i < 2; i++)
#pragma unroll
        for (int j = 0; j < 8; j++)
#pragma unroll
            for (int v = 0; v < 4; v++) acc[i][j][v] = 0.f;

    gemm_main<1>(Ah, Ah, Bw, D_, m0, n0, sb, acc);

    const int fr = lane >> 2, fc = (lane & 3) * 2;
#pragma unroll
    for (int i = 0; i < 2; i++) {
#pragma unroll
        for (int j = 0; j < 8; j++) {
            int row = m0 + wm + i * 16 + fr;       // global b*S + s
            int col = n0 + wn + j * 8 + fc;        // kvh*128 + d (even)
            int b = row >> 11, s = row & (S_ - 1);
            size_t base = ((size_t)((b * KVH_) * 128 + col)) * S_ + s;
            // col and col+1 stay within the same kvh (col even, never ..127)
            Vt[base]          = __float2half(acc[i][j][0]);
            Vt[base + S_]     = __float2half(acc[i][j][1]);
            Vt[base + 8]      = __float2half(acc[i][j][2]);
            Vt[base + S_ + 8] = __float2half(acc[i][j][3]);
        }
    }
}

// Fused RoPE + head-permute epilogue, fp16 out (optional hi/lo split),
// with prescale folded in. Templated A-split.
template <int ASPLIT>
__global__ void __launch_bounds__(256, 2)
gemm_hmma_rope_h(const __half* __restrict__ Ah, const __half* __restrict__ Al,
                 const __half* __restrict__ Bw,
                 __half* __restrict__ Ohi, __half* __restrict__ Olo,
                 const float* __restrict__ fcos, const float* __restrict__ fsin,
                 int heads, int do_split, float prescale, int M, int N, int K) {
    extern __shared__ __half dsm[];
    const uint32_t sb = smem_u32(dsm);
    const int lane = threadIdx.x & 31, wid = threadIdx.x >> 5;
    const int wm = (wid & 3) * 32, wn = (wid >> 2) * 64;
    const int m0 = blockIdx.y * 128, n0 = blockIdx.x * 128;

    float acc[2][8][4];
#pragma unroll
    for (int i = 0; i < 2; i++)
#pragma unroll
        for (int j = 0; j < 8; j++)
#pragma unroll
            for (int v = 0; v < 4; v++) acc[i][j][v] = 0.f;

    gemm_main<ASPLIT>(Ah, Al, Bw, K, m0, n0, sb, acc);

    const int fr = lane >> 2, fc = (lane & 3) * 2;
#pragma unroll
    for (int i = 0; i < 2; i++) {
#pragma unroll
        for (int j = 0; j < 8; j++) {
            int col = n0 + wn + j * 8 + fc;      // even
            int hh = col >> 7, d = col & 127, ip = d >> 1;
#pragma unroll
            for (int rsel = 0; rsel < 2; rsel++) {
                int r = m0 + wm + i * 16 + fr + rsel * 8;
                int s = r & (S_ - 1), bb = r >> 11;
                float c = fcos[s * 64 + ip], sn = fsin[s * 64 + ip];
                float a = acc[i][j][rsel * 2 + 0];
                float b2 = acc[i][j][rsel * 2 + 1];
                float ra = (a * c - b2 * sn) * prescale;
                float rb = (a * sn + b2 * c) * prescale;
                size_t o = (((size_t)(bb * heads + hh) * S_) + s) * 128 + d;
                __half2 h2 = __floats2half2_rn(ra, rb);
                *(uint32_t*)(Ohi + o) = *reinterpret_cast<uint32_t*>(&h2);
                if (do_split) {
                    __half2 l2 = __floats2half2_rn(ra - __half2float(h2.x),
                                                   rb - __half2float(h2.y));
                    *(uint32_t*)(Olo + o) = *reinterpret_cast<uint32_t*>(&l2);
                }
            }
        }
    }
}

// ---------------------------------------------------------------------------
// HMMA flash attention (best-measured shape): 256 threads / 128 q-rows,
// base-2 scores (Q prescaled), fp32 ex2 softmax, l via ones-MMA,
// conditional rescale, per-warp mask skip, cp.async 2-stage K/V, fp16 out.
// ---------------------------------------------------------------------------
#define QSTRD 136
#define VSTRD 72
#define KV_STG_H (64 * QSTRD + 128 * VSTRD)
#define ATTN_SMEM ((2 * 128 * QSTRD + 2 * KV_STG_H) * 2)

__global__ void __launch_bounds__(256, 1)
attn_hmma(const __half* __restrict__ Qh, const __half* __restrict__ Ql,
          const __half* __restrict__ Kh, const __half* __restrict__ Vt16,
          __half* __restrict__ O16) {
    extern __shared__ __half hsm[];
    __half* sQh = hsm;
    __half* sQl = sQh + 128 * QSTRD;
    __half* kvs = sQl + 128 * QSTRD;

    const uint32_t sQh_a = smem_u32(sQh);
    const uint32_t sQl_a = smem_u32(sQl);
    const uint32_t kv_a  = smem_u32(kvs);

    const int tid = threadIdx.x;
    const int lane = tid & 31, wid = tid >> 5;
    const int h  = blockIdx.x;
    const int bx = (gridDim.y - 1) - blockIdx.y;   // heavy tiles first
    const int b  = blockIdx.z;
    const int q0 = bx * 128;
    const int kvh = h >> 2;
    const int fr = lane >> 2, fc2 = (lane & 3) * 2;
    const int wr0 = wid * 16;

    {
        const size_t qg = (((size_t)(b * H_ + h) * S_) + q0) * 128;
#pragma unroll
        for (int it = 0; it < 8; it++) {
            int idx = tid + it * 256;
            int row = idx >> 4, c8 = (idx & 15) * 8;
            *(uint4*)&sQh[row * QSTRD + c8] = *(const uint4*)(Qh + qg + (size_t)row * 128 + c8);
            *(uint4*)&sQl[row * QSTRD + c8] = *(const uint4*)(Ql + qg + (size_t)row * 128 + c8);
        }
    }

    const size_t kgb = ((size_t)(b * KVH_ + kvh) * S_) * 128;
    const size_t vgb = ((size_t)(b * KVH_ + kvh) * 128) * S_;

    auto load_kv = [&](int kt, int stg) {
        uint32_t sa = kv_a + (uint32_t)(stg * KV_STG_H) * 2;
        const int k0 = kt * 64;
#pragma unroll
        for (int it = 0; it < 4; it++) {
            int idx = tid + it * 256;
            int row = idx >> 4, c8 = (idx & 15) * 8;
            CP16(sa + (uint32_t)(row * QSTRD + c8) * 2,
                 Kh + kgb + (size_t)(k0 + row) * 128 + c8);
        }
#pragma unroll
        for (int it = 0; it < 4; it++) {
            int idx = tid + it * 256;
            int row = idx >> 3, c8 = (idx & 7) * 8;
            CP16(sa + 64*QSTRD*2 + (uint32_t)(row * VSTRD + c8) * 2,
                 Vt16 + vgb + (size_t)row * S_ + k0 + c8);
        }
        CP_COMMIT();
    };

    float o_acc[16][4];
#pragma unroll
    for (int j = 0; j < 16; j++)
#pragma unroll
        for (int c = 0; c < 4; c++) o_acc[j][c] = 0.f;
    float l_acc[4] = {0.f, 0.f, 0.f, 0.f};
    float m0 = -1e30f, m1 = -1e30f;

    const int ntiles = 2 * bx + 2;
    const int r0g = q0 + wr0 + fr, r1g = r0g + 8;

    const int arow_in = lane & 15, acol_add = (lane >> 4) * 8;
    const int brow_in = (lane >> 4) * 8 + (lane & 7);
    const int bcol_add = ((lane >> 3) & 1) * 8;
    const uint32_t ONES = 0x3C003C00u;

    load_kv(0, 0);
    __syncthreads();

    for (int kt = 0; kt < ntiles; kt++) {
        const int k0 = kt * 64;
        const int stg = kt & 1;
        if (kt + 1 < ntiles) {
            load_kv(kt + 1, stg ^ 1);
            asm volatile("cp.async.wait_group 1;" ::: "memory");
        } else {
            asm volatile("cp.async.wait_group 0;" ::: "memory");
        }
        __syncthreads();

        const uint32_t sK_a = kv_a + (uint32_t)(stg * KV_STG_H) * 2;
        const uint32_t sV_a = sK_a + 64*QSTRD*2;

        // ---- QK^T (base-2 domain) ----
        float s[8][4];
#pragma unroll
        for (int j = 0; j < 8; j++)
#pragma unroll
            for (int c = 0; c < 4; c++) s[j][c] = 0.f;

#pragma unroll
        for (int kk = 0; kk < 8; kk++) {
            const int kkc = kk * 16;
            uint32_t ah[4], al[4];
            uint32_t ao = (uint32_t)((wr0 + arow_in) * QSTRD + kkc + acol_add) * 2;
            LDSM4(ah[0], ah[1], ah[2], ah[3], sQh_a + ao);
            LDSM4(al[0], al[1], al[2], al[3], sQl_a + ao);
#pragma unroll
            for (int jp = 0; jp < 4; jp++) {
                uint32_t bo = (uint32_t)((jp * 16 + brow_in) * QSTRD + kkc + bcol_add) * 2;
                uint32_t bh[4];
                LDSM4(bh[0], bh[1], bh[2], bh[3], sK_a + bo);
                mma16816h(s[2*jp],   ah, bh[0], bh[1]);
                mma16816h(s[2*jp],   al, bh[0], bh[1]);
                mma16816h(s[2*jp+1], ah, bh[2], bh[3]);
                mma16816h(s[2*jp+1], al, bh[2], bh[3]);
            }
        }

        // ---- mask (skip fully-causal tiles for this warp) ----
        if (k0 + 63 > q0 + wr0) {
#pragma unroll
            for (int j = 0; j < 8; j++) {
                int c0g = k0 + j * 8 + fc2, c1g = c0g + 1;
                s[j][0] = (c0g <= r0g) ? s[j][0] : 0.f;
                s[j][1] = (c1g <= r0g) ? s[j][1] : 0.f;
                s[j][2] = (c0g <= r1g) ? s[j][2] : 0.f;
                s[j][3] = (c1g <= r1g) ? s[j][3] : 0.f;
            }
        }

        // ---- row max ----
        float rm0 = -1e30f, rm1 = -1e30f;
#pragma unroll
        for (int j = 0; j < 8; j++) {
            rm0 = fmaxf(rm0, fmaxf(s[j][0], s[j][1]));
            rm1 = fmaxf(rm1, fmaxf(s[j][2], s[j][3]));
        }
        rm0 = fmaxf(rm0, __shfl_xor_sync(0xffffffffu, rm0, 1));
        rm0 = fmaxf(rm0, __shfl_xor_sync(0xffffffffu, rm0, 2));
        rm1 = fmaxf(rm1, __shfl_xor_sync(0xffffffffu, rm1, 1));
        rm1 = fmaxf(rm1, __shfl_xor_sync(0xffffffffu, rm1, 2));

        float mn0 = fmaxf(m0, rm0), mn1 = fmaxf(m1, rm1);
        if (mn0 > m0 || mn1 > m1) {
            float f0 = ex2f(m0 - mn0), f1 = ex2f(m1 - mn1);
#pragma unroll
            for (int j = 0; j < 16; j++) {
                o_acc[j][0] *= f0; o_acc[j][1] *= f0;
                o_acc[j][2] *= f1; o_acc[j][3] *= f1;
            }
            l_acc[0] *= f0; l_acc[1] *= f0;
            l_acc[2] *= f1; l_acc[3] *= f1;
            m0 = mn0; m1 = mn1;
        }

        // ---- P = exp2(s - m), fp32 ex2 then pack ----
        uint32_t P0[8], P1[8];
#pragma unroll
        for (int j = 0; j < 8; j++) {
            P0[j] = pkh(ex2f(s[j][0] - m0), ex2f(s[j][1] - m0));
            P1[j] = pkh(ex2f(s[j][2] - m1), ex2f(s[j][3] - m1));
        }

        // ---- P @ V + l (ones-column MMA) ----
#pragma unroll
        for (int kk2 = 0; kk2 < 4; kk2++) {
            uint32_t ph[4] = {P0[2*kk2], P1[2*kk2], P0[2*kk2+1], P1[2*kk2+1]};
            mma16816h(l_acc, ph, ONES, ONES);
#pragma unroll
            for (int jp2 = 0; jp2 < 8; jp2++) {
                uint32_t vo = (uint32_t)((jp2 * 16 + brow_in) * VSTRD + kk2 * 16 + bcol_add) * 2;
                uint32_t vh[4];
                LDSM4(vh[0], vh[1], vh[2], vh[3], sV_a + vo);
                mma16816h(o_acc[2*jp2],   ph, vh[0], vh[1]);
                mma16816h(o_acc[2*jp2+1], ph, vh[2], vh[3]);
            }
        }
        __syncthreads();
    }

    float l0 = l_acc[0], l1 = l_acc[2];

    // ---- analytic masked tail ----
    const int n_tail = S_ - (q0 + 128);
    if (n_tail > 0) {
        const float* suf = g_vsuf + ((size_t)(ntiles * B_ + b) * KVH_ + kvh) * HD_;
        float mn0 = fmaxf(m0, 0.f), mn1 = fmaxf(m1, 0.f);
        float f0 = ex2f(m0 - mn0), f1 = ex2f(m1 - mn1);
        float pt0 = ex2f(0.f - mn0), pt1 = ex2f(0.f - mn1);
        l0 = l0 * f0 + (float)n_tail * pt0;
        l1 = l1 * f1 + (float)n_tail * pt1;
#pragma unroll
        for (int j2 = 0; j2 < 16; j2++) {
            float2 sv = *(const float2*)(suf + j2 * 8 + fc2);
            o_acc[j2][0] = o_acc[j2][0] * f0 + pt0 * sv.x;
            o_acc[j2][1] = o_acc[j2][1] * f0 + pt0 * sv.y;
            o_acc[j2][2] = o_acc[j2][2] * f1 + pt1 * sv.x;
            o_acc[j2][3] = o_acc[j2][3] * f1 + pt1 * sv.y;
        }
    }

    // ---- normalize + write fp16 [b, s, h*128 + d] ----
    const float inv0 = 1.f / l0, inv1 = 1.f / l1;
    const size_t ob0 = (size_t)(b * S_ + r0g) * (H_ * HD_) + h * HD_;
    const size_t ob1 = (size_t)(b * S_ + r1g) * (H_ * HD_) + h * HD_;
#pragma unroll
    for (int j2 = 0; j2 < 16; j2++) {
        int d = j2 * 8 + fc2;
        *(uint32_t*)(O16 + ob0 + d) = pkh(o_acc[j2][0] * inv0, o_acc[j2][1] * inv0);
        *(uint32_t*)(O16 + ob1 + d) = pkh(o_acc[j2][2] * inv1, o_acc[j2][3] * inv1);
    }
}

// ---------------------------------------------------------------------------
// Inputs: 0:x 1:freqs_cos 2:freqs_sin 3:mask 4:wq 5:wk 6:wv 7:wo
//         8:cache_k 9:cache_v 10:start_pos
// ---------------------------------------------------------------------------
extern "C" void kernel_launch(void* const* d_in, const int* in_sizes, int n_in,
                              void* d_out, int out_size) {
    const float* x    = (const float*)d_in[0];
    const float* fcos = (const float*)d_in[1];
    const float* fsin = (const float*)d_in[2];
    const float* wq   = (const float*)d_in[4];
    const float* wk   = (const float*)d_in[5];
    const float* wv   = (const float*)d_in[6];
    const float* wo   = (const float*)d_in[7];
    float* out = (float*)d_out;

    __half *xh, *xl, *wqT, *wkT, *wvT, *woT, *ah;
    __half *qch, *qcl, *kch, *vt16;
    cudaGetSymbolAddress((void**)&xh,  g_xh);
    cudaGetSymbolAddress((void**)&xl,  g_xl);
    cudaGetSymbolAddress((void**)&wqT, g_wqT);
    cudaGetSymbolAddress((void**)&wkT, g_wkT);
    cudaGetSymbolAddress((void**)&wvT, g_wvT);
    cudaGetSymbolAddress((void**)&woT, g_woT);
    cudaGetSymbolAddress((void**)&ah,  g_ah);
    cudaGetSymbolAddress((void**)&qch, g_qch);
    cudaGetSymbolAddress((void**)&qcl, g_qcl);
    cudaGetSymbolAddress((void**)&kch, g_kch);
    cudaGetSymbolAddress((void**)&vt16, g_vt16);

    const int M = B_ * S_;
    const int NQ = H_ * HD_;
    const int NKV = KVH_ * HD_;

    cudaFuncSetAttribute(gemm_hmma<1>, cudaFuncAttributeMaxDynamicSharedMemorySize,
                         GSMEM_1);
    cudaFuncSetAttribute(gemm_vproj, cudaFuncAttributeMaxDynamicSharedMemorySize,
                         GSMEM_1);
    cudaFuncSetAttribute(gemm_hmma_rope_h<1>, cudaFuncAttributeMaxDynamicSharedMemorySize,
                         GSMEM_1);
    cudaFuncSetAttribute(gemm_hmma_rope_h<2>, cudaFuncAttributeMaxDynamicSharedMemorySize,
                         GSMEM_2);
    cudaFuncSetAttribute(attn_hmma, cudaFuncAttributeMaxDynamicSharedMemorySize,
                         ATTN_SMEM);

    // 1: activation split
    {
        int n4 = M * D_ / 4;
        split_conv_h<<<(n4 + 255) / 256, 256>>>((const float4*)x, xh, xl, n4);
    }
    // 2: all weight transposes in one launch
    transp_all<<<40960, dim3(32, 8)>>>(wq, wk, wv, wo, wqT, wkT, wvT, woT);

    // 3: Q projection — single-A fp16, fused RoPE, fp16 hi/lo out
    gemm_hmma_rope_h<1><<<dim3(NQ / 128, M / 128), 256, GSMEM_1>>>(
        xh, xh, wqT, qch, qcl, fcos, fsin, H_, 1, SCALE_L2E, M, NQ, D_);
    // 4: K projection — A-split x2
    gemm_hmma_rope_h<2><<<dim3(NKV / 128, M / 128), 256, GSMEM_2>>>(
        xh, xl, wkT, kch, kch, fcos, fsin, KVH_, 0, 1.0f, M, NKV, D_);
    // 5: V projection — single-A, writes transposed fp16 directly
    gemm_vproj<<<dim3(NKV / 128, M / 128), 256, GSMEM_1>>>(xh, wvT, vt16);

    // 6-7: suffix V sums (from fp16 transposed V)
    vtile_sums<<<dim3(32, B_ * KVH_), 128>>>(vt16);
    vsuffix_scan<<<8, 256>>>();

    // 8: attention
    attn_hmma<<<dim3(H_, S_ / 128, B_), 256, ATTN_SMEM>>>(qch, qcl, kch, vt16, ah);

    // 9: output projection (single-A, output-linear)
    gemm_hmma<1><<<dim3(D_ / 128, M / 128), 256, GSMEM_1>>>(
        ah, ah, woT, out, M, D_, D_);
}

// round 17
// speedup vs baseline: 1.0688x; 1.0596x over previous
#include <cuda_runtime.h>
#include <cuda_bf16.h>
#include <cuda_fp16.h>
#include <cstdint>
#include <math.h>

#define B_    2
#define S_    2048
#define D_    4096
#define H_    32
#define KVH_  8
#define HD_   128
#define HALF_ 64

// 1/sqrt(128) * log2(e): Q prescale so scores are in base-2 domain
#define SCALE_L2E 0.1275174455f

// ---------------------------------------------------------------------------
// Scratch (__device__ globals; allocation-free rule)
// ---------------------------------------------------------------------------
__device__ float g_vtile[(size_t)32*B_*KVH_*HD_];
__device__ float g_vsuf[(size_t)33*B_*KVH_*HD_];

__device__ __half g_xh[(size_t)B_*S_*D_];
__device__ __half g_wqT[(size_t)D_*H_*HD_];
__device__ __half g_wkT[(size_t)D_*KVH_*HD_];
__device__ __half g_wvT[(size_t)D_*KVH_*HD_];
__device__ __half g_woT[(size_t)D_*H_*HD_];
__device__ __half g_ah[(size_t)B_*S_*H_*HD_];

// Attention operands: Q fp16 hi/lo (prescaled), K single fp16, V fp16
__device__ __half g_qch[(size_t)B_*H_*S_*HD_];
__device__ __half g_qcl[(size_t)B_*H_*S_*HD_];
__device__ __half g_kch[(size_t)B_*KVH_*S_*HD_];
__device__ __half g_vt16[(size_t)B_*KVH_*HD_*S_];   // [b,kvh,d,s]

// ---------------------------------------------------------------------------
// PTX helpers
// ---------------------------------------------------------------------------
__device__ __forceinline__ void mma16816h(float* c, const uint32_t* a,
                                          uint32_t b0, uint32_t b1) {
    asm volatile(
        "mma.sync.aligned.m16n8k16.row.col.f32.f16.f16.f32 "
        "{%0,%1,%2,%3}, {%4,%5,%6,%7}, {%8,%9}, {%0,%1,%2,%3};"
        : "+f"(c[0]), "+f"(c[1]), "+f"(c[2]), "+f"(c[3])
        : "r"(a[0]), "r"(a[1]), "r"(a[2]), "r"(a[3]), "r"(b0), "r"(b1));
}
#define LDSM4(R0, R1, R2, R3, ADDR) \
    asm volatile("ldmatrix.sync.aligned.m8n8.x4.shared.b16 {%0,%1,%2,%3}, [%4];" \
        : "=r"(R0), "=r"(R1), "=r"(R2), "=r"(R3) : "r"(ADDR))

__device__ __forceinline__ uint32_t smem_u32(const void* p) {
    uint32_t a;
    asm("{ .reg .u64 t; cvta.to.shared.u64 t, %1; cvt.u32.u64 %0, t; }"
        : "=r"(a) : "l"(p));
    return a;
}
#define CP16(dst, src) \
    asm volatile("cp.async.cg.shared.global [%0], [%1], 16;" \
        :: "r"(dst), "l"(src) : "memory")
#define CP_COMMIT() asm volatile("cp.async.commit_group;" ::: "memory")

__device__ __forceinline__ uint32_t pkh(float a, float b) {
    __half2 t = __floats2half2_rn(a, b);
    return *reinterpret_cast<uint32_t*>(&t);
}
__device__ __forceinline__ float ex2f(float a) {
    float d;
    asm("ex2.approx.f32 %0, %1;" : "=f"(d) : "f"(a));
    return d;
}

// ---------------------------------------------------------------------------
// Conversion kernels
// ---------------------------------------------------------------------------
__global__ void conv_h(const float4* __restrict__ in,
                       __half* __restrict__ o16, int n4) {
    int i = blockIdx.x * blockDim.x + threadIdx.x;
    if (i >= n4) return;
    float4 v = in[i];
    uint2 hv = {pkh(v.x, v.y), pkh(v.z, v.w)};
    *(uint2*)(o16 + i * 4) = hv;
}

// All four weight transposes in one launch: wq, wk, wv, wo.
__global__ void transp_all(const float* __restrict__ wq, const float* __restrict__ wk,
                           const float* __restrict__ wv, const float* __restrict__ wo,
                           __half* __restrict__ wqT, __half* __restrict__ wkT,
                           __half* __restrict__ wvT, __half* __restrict__ woT) {
    __shared__ float t[32][33];
    int bid = blockIdx.x;
    const float* in; __half* out; int R, C;
    if (bid < 16384)      { in = wq; out = wqT; R = 4096; C = 4096; }
    else if (bid < 20480) { bid -= 16384; in = wk; out = wkT; R = 4096; C = 1024; }
    else if (bid < 24576) { bid -= 20480; in = wv; out = wvT; R = 4096; C = 1024; }
    else                  { bid -= 24576; in = wo; out = woT; R = 4096; C = 4096; }
    int cb = bid % (C / 32), rb = bid / (C / 32);
    int c0 = cb * 32, r0 = rb * 32;
    int x = threadIdx.x, y = threadIdx.y;   // 32 x 8
#pragma unroll
    for (int j = 0; j < 32; j += 8)
        t[y + j][x] = in[(size_t)(r0 + y + j) * C + c0 + x];
    __syncthreads();
#pragma unroll
    for (int j = 0; j < 32; j += 8)
        out[(size_t)(c0 + y + j) * R + r0 + x] = __float2half(t[x][y + j]);
}

// ---------------------------------------------------------------------------
// Suffix-V from fp16 transposed V: [b,kvh,d,s]
// ---------------------------------------------------------------------------
__global__ void vtile_sums(const __half* __restrict__ V16) {
    int d = threadIdx.x;
    int t = blockIdx.x;
    int kvh = blockIdx.y & 7, b = blockIdx.y >> 3;
    const __half* p = V16 + ((size_t)((b * KVH_ + kvh) * 128 + d)) * S_ + t * 64;
    float acc = 0.f;
#pragma unroll 8
    for (int k = 0; k < 64; k++)
        acc += __half2float(p[k]);
    g_vtile[((size_t)(t * B_ + b) * KVH_ + kvh) * HD_ + d] = acc;
}
__global__ void vsuffix_scan() {
    int idx = blockIdx.x * blockDim.x + threadIdx.x;
    int d = idx & 127, kvh = (idx >> 7) & 7, b = idx >> 10;
    float acc = 0.f;
    g_vsuf[((size_t)(32 * B_ + b) * KVH_ + kvh) * HD_ + d] = 0.f;
    for (int t = 31; t >= 0; t--) {
        acc += g_vtile[((size_t)(t * B_ + b) * KVH_ + kvh) * HD_ + d];
        g_vsuf[((size_t)(t * B_ + b) * KVH_ + kvh) * HD_ + d] = acc;
    }
}

// ---------------------------------------------------------------------------
// GEMM mainloop: fp16 single-A, 128x128 tile, BK=64, 8 warps,
// cp.async 2-stage, ldmatrix. C = A[M,K] @ B[N,K]^T.
// ---------------------------------------------------------------------------
#define STRG 72
#define GSMEM_1 (2 * (2 * 128 * STRG) * 2)   // 73728 B

__device__ __forceinline__ void gemm_main(
    const __half* __restrict__ Ah, const __half* __restrict__ Bw,
    int K, int m0, int n0, uint32_t sb, float acc[2][8][4])
{
    const int tid = threadIdx.x;
    const int lane = tid & 31, wid = tid >> 5;
    const int wm = (wid & 3) * 32, wn = (wid >> 2) * 64;
    const uint32_t GST = (uint32_t)(2 * 128 * STRG);
    const int NC = K / 64;

    const int lrow = tid >> 3, lcg = (tid & 7) * 8;   // 128 rows x 64 cols

    auto load_stage = [&](int s, int k0) {
        uint32_t sa = sb + (uint32_t)s * GST * 2;
#pragma unroll
        for (int it = 0; it < 4; it++) {
            int row = lrow + it * 32;
            size_t ga = (size_t)(m0 + row) * K + k0 + lcg;
            size_t gb = (size_t)(n0 + row) * K + k0 + lcg;
            uint32_t o = (uint32_t)(row * STRG + lcg) * 2;
            CP16(sa + o, Ah + ga);
            CP16(sa + (uint32_t)(128 * STRG) * 2 + o, Bw + gb);
        }
        CP_COMMIT();
    };

    load_stage(0, 0);

    const int arow_in = lane & 15, acol_add = (lane >> 4) * 8;
    const int brow_in = (lane >> 4) * 8 + (lane & 7);
    const int bcol_add = ((lane >> 3) & 1) * 8;

    for (int i = 0; i < NC; i++) {
        if (i + 1 < NC) {
            load_stage((i + 1) & 1, (i + 1) * 64);
            asm volatile("cp.async.wait_group 1;" ::: "memory");
        } else {
            asm volatile("cp.async.wait_group 0;" ::: "memory");
        }
        __syncthreads();

        uint32_t sbase = sb + (uint32_t)((i & 1) * GST) * 2;

#pragma unroll
        for (int kk2 = 0; kk2 < 4; kk2++) {
            const int kkc = kk2 * 16;
            uint32_t ah[2][4];
#pragma unroll
            for (int ii = 0; ii < 2; ii++) {
                uint32_t ao = (uint32_t)((wm + ii * 16 + arow_in) * STRG + kkc + acol_add) * 2;
                LDSM4(ah[ii][0], ah[ii][1], ah[ii][2], ah[ii][3], sbase + ao);
            }
            uint32_t bh[4][4];
#pragma unroll
            for (int jp = 0; jp < 4; jp++) {
                uint32_t bo = (uint32_t)((wn + jp * 16 + brow_in) * STRG + kkc + bcol_add) * 2;
                LDSM4(bh[jp][0], bh[jp][1], bh[jp][2], bh[jp][3],
                      sbase + (uint32_t)(128 * STRG) * 2 + bo);
            }
#pragma unroll
            for (int jp = 0; jp < 4; jp++) {
#pragma unroll
                for (int ii = 0; ii < 2; ii++) {
                    mma16816h(acc[ii][2*jp],   ah[ii], bh[jp][0], bh[jp][1]);
                    mma16816h(acc[ii][2*jp+1], ah[ii], bh[jp][2], bh[jp][3]);
                }
            }
        }
        __syncthreads();
    }
}

// Plain fp32 epilogue (O projection)
__global__ void __launch_bounds__(256, 2)
gemm_hmma(const __half* __restrict__ Ah, const __half* __restrict__ Bw,
          float* __restrict__ C, int M, int N, int K) {
    extern __shared__ __half dsm[];
    const uint32_t sb = smem_u32(dsm);
    const int lane = threadIdx.x & 31, wid = threadIdx.x >> 5;
    const int wm = (wid & 3) * 32, wn = (wid >> 2) * 64;
    const int m0 = blockIdx.y * 128, n0 = blockIdx.x * 128;

    float acc[2][8][4];
#pragma unroll
    for (int i = 0; i < 2; i++)
#pragma unroll
        for (int j = 0; j < 8; j++)
#pragma unroll
            for (int v = 0; v < 4; v++) acc[i][j][v] = 0.f;

    gemm_main(Ah, Bw, K, m0, n0, sb, acc);

    const int fr = lane >> 2, fc = (lane & 3) * 2;
#pragma unroll
    for (int i = 0; i < 2; i++) {
#pragma unroll
        for (int j = 0; j < 8; j++) {
            int row = m0 + wm + i * 16 + fr;
            int col = n0 + wn + j * 8 + fc;
            float2 v0 = {acc[i][j][0], acc[i][j][1]};
            float2 v1 = {acc[i][j][2], acc[i][j][3]};
            *(float2*)&C[(size_t)row * N + col] = v0;
            *(float2*)&C[(size_t)(row + 8) * N + col] = v1;
        }
    }
}

// V projection: epilogue writes TRANSPOSED fp16 directly into [b,kvh,d,s].
__global__ void __launch_bounds__(256, 2)
gemm_vproj(const __half* __restrict__ Ah, const __half* __restrict__ Bw,
           __half* __restrict__ Vt) {
    extern __shared__ __half dsm[];
    const uint32_t sb = smem_u32(dsm);
    const int lane = threadIdx.x & 31, wid = threadIdx.x >> 5;
    const int wm = (wid & 3) * 32, wn = (wid >> 2) * 64;
    const int m0 = blockIdx.y * 128, n0 = blockIdx.x * 128;

    float acc[2][8][4];
#pragma unroll
    for (int i = 0; i < 2; i++)
#pragma unroll
        for (int j = 0; j < 8; j++)
#pragma unroll
            for (int v = 0; v < 4; v++) acc[i][j][v] = 0.f;

    gemm_main(Ah, Bw, D_, m0, n0, sb, acc);

    const int fr = lane >> 2, fc = (lane & 3) * 2;
#pragma unroll
    for (int i = 0; i < 2; i++) {
#pragma unroll
        for (int j = 0; j < 8; j++) {
            int row = m0 + wm + i * 16 + fr;       // global b*S + s
            int col = n0 + wn + j * 8 + fc;        // kvh*128 + d (even)
            int b = row >> 11, s = row & (S_ - 1);
            size_t base = ((size_t)((b * KVH_) * 128 + col)) * S_ + s;
            Vt[base]          = __float2half(acc[i][j][0]);
            Vt[base + S_]     = __float2half(acc[i][j][1]);
            Vt[base + 8]      = __float2half(acc[i][j][2]);
            Vt[base + S_ + 8] = __float2half(acc[i][j][3]);
        }
    }
}

// Fused RoPE + head-permute epilogue, fp16 out (optional hi/lo split),
// with prescale folded in. Single-A mainloop.
__global__ void __launch_bounds__(256, 2)
gemm_hmma_rope_h(const __half* __restrict__ Ah, const __half* __restrict__ Bw,
                 __half* __restrict__ Ohi, __half* __restrict__ Olo,
                 const float* __restrict__ fcos, const float* __restrict__ fsin,
                 int heads, int do_split, float prescale, int M, int N, int K) {
    extern __shared__ __half dsm[];
    const uint32_t sb = smem_u32(dsm);
    const int lane = threadIdx.x & 31, wid = threadIdx.x >> 5;
    const int wm = (wid & 3) * 32, wn = (wid >> 2) * 64;
    const int m0 = blockIdx.y * 128, n0 = blockIdx.x * 128;

    float acc[2][8][4];
#pragma unroll
    for (int i = 0; i < 2; i++)
#pragma unroll
        for (int j = 0; j < 8; j++)
#pragma unroll
            for (int v = 0; v < 4; v++) acc[i][j][v] = 0.f;

    gemm_main(Ah, Bw, K, m0, n0, sb, acc);

    const int fr = lane >> 2, fc = (lane & 3) * 2;
#pragma unroll
    for (int i = 0; i < 2; i++) {
#pragma unroll
        for (int j = 0; j < 8; j++) {
            int col = n0 + wn + j * 8 + fc;      // even
            int hh = col >> 7, d = col & 127, ip = d >> 1;
#pragma unroll
            for (int rsel = 0; rsel < 2; rsel++) {
                int r = m0 + wm + i * 16 + fr + rsel * 8;
                int s = r & (S_ - 1), bb = r >> 11;
                float c = fcos[s * 64 + ip], sn = fsin[s * 64 + ip];
                float a = acc[i][j][rsel * 2 + 0];
                float b2 = acc[i][j][rsel * 2 + 1];
                float ra = (a * c - b2 * sn) * prescale;
                float rb = (a * sn + b2 * c) * prescale;
                size_t o = (((size_t)(bb * heads + hh) * S_) + s) * 128 + d;
                __half2 h2 = __floats2half2_rn(ra, rb);
                *(uint32_t*)(Ohi + o) = *reinterpret_cast<uint32_t*>(&h2);
                if (do_split) {
                    __half2 l2 = __floats2half2_rn(ra - __half2float(h2.x),
                                                   rb - __half2float(h2.y));
                    *(uint32_t*)(Olo + o) = *reinterpret_cast<uint32_t*>(&l2);
                }
            }
        }
    }
}

// ---------------------------------------------------------------------------
// HMMA flash attention (best-measured shape): 256 threads / 128 q-rows,
// base-2 scores (Q prescaled), fp32 ex2 softmax, l via ones-MMA,
// conditional rescale, per-warp mask skip, cp.async 2-stage K/V, fp16 out.
// ---------------------------------------------------------------------------
#define QSTRD 136
#define VSTRD 72
#define KV_STG_H (64 * QSTRD + 128 * VSTRD)
#define ATTN_SMEM ((2 * 128 * QSTRD + 2 * KV_STG_H) * 2)

__global__ void __launch_bounds__(256, 1)
attn_hmma(const __half* __restrict__ Qh, const __half* __restrict__ Ql,
          const __half* __restrict__ Kh, const __half* __restrict__ Vt16,
          __half* __restrict__ O16) {
    extern __shared__ __half hsm[];
    __half* sQh = hsm;
    __half* sQl = sQh + 128 * QSTRD;
    __half* kvs = sQl + 128 * QSTRD;

    const uint32_t sQh_a = smem_u32(sQh);
    const uint32_t sQl_a = smem_u32(sQl);
    const uint32_t kv_a  = smem_u32(kvs);

    const int tid = threadIdx.x;
    const int lane = tid & 31, wid = tid >> 5;
    const int h  = blockIdx.x;
    const int bx = (gridDim.y - 1) - blockIdx.y;   // heavy tiles first
    const int b  = blockIdx.z;
    const int q0 = bx * 128;
    const int kvh = h >> 2;
    const int fr = lane >> 2, fc2 = (lane & 3) * 2;
    const int wr0 = wid * 16;

    {
        const size_t qg = (((size_t)(b * H_ + h) * S_) + q0) * 128;
#pragma unroll
        for (int it = 0; it < 8; it++) {
            int idx = tid + it * 256;
            int row = idx >> 4, c8 = (idx & 15) * 8;
            *(uint4*)&sQh[row * QSTRD + c8] = *(const uint4*)(Qh + qg + (size_t)row * 128 + c8);
            *(uint4*)&sQl[row * QSTRD + c8] = *(const uint4*)(Ql + qg + (size_t)row * 128 + c8);
        }
    }

    const size_t kgb = ((size_t)(b * KVH_ + kvh) * S_) * 128;
    const size_t vgb = ((size_t)(b * KVH_ + kvh) * 128) * S_;

    auto load_kv = [&](int kt, int stg) {
        uint32_t sa = kv_a + (uint32_t)(stg * KV_STG_H) * 2;
        const int k0 = kt * 64;
#pragma unroll
        for (int it = 0; it < 4; it++) {
            int idx = tid + it * 256;
            int row = idx >> 4, c8 = (idx & 15) * 8;
            CP16(sa + (uint32_t)(row * QSTRD + c8) * 2,
                 Kh + kgb + (size_t)(k0 + row) * 128 + c8);
        }
#pragma unroll
        for (int it = 0; it < 4; it++) {
            int idx = tid + it * 256;
            int row = idx >> 3, c8 = (idx & 7) * 8;
            CP16(sa + 64*QSTRD*2 + (uint32_t)(row * VSTRD + c8) * 2,
                 Vt16 + vgb + (size_t)row * S_ + k0 + c8);
        }
        CP_COMMIT();
    };

    float o_acc[16][4];
#pragma unroll
    for (int j = 0; j < 16; j++)
#pragma unroll
        for (int c = 0; c < 4; c++) o_acc[j][c] = 0.f;
    float l_acc[4] = {0.f, 0.f, 0.f, 0.f};
    float m0 = -1e30f, m1 = -1e30f;

    const int ntiles = 2 * bx + 2;
    const int r0g = q0 + wr0 + fr, r1g = r0g + 8;

    const int arow_in = lane & 15, acol_add = (lane >> 4) * 8;
    const int brow_in = (lane >> 4) * 8 + (lane & 7);
    const int bcol_add = ((lane >> 3) & 1) * 8;
    const uint32_t ONES = 0x3C003C00u;

    load_kv(0, 0);
    __syncthreads();

    for (int kt = 0; kt < ntiles; kt++) {
        const int k0 = kt * 64;
        const int stg = kt & 1;
        if (kt + 1 < ntiles) {
            load_kv(kt + 1, stg ^ 1);
            asm volatile("cp.async.wait_group 1;" ::: "memory");
        } else {
            asm volatile("cp.async.wait_group 0;" ::: "memory");
        }
        __syncthreads();

        const uint32_t sK_a = kv_a + (uint32_t)(stg * KV_STG_H) * 2;
        const uint32_t sV_a = sK_a + 64*QSTRD*2;

        // ---- QK^T (base-2 domain) ----
        float s[8][4];
#pragma unroll
        for (int j = 0; j < 8; j++)
#pragma unroll
            for (int c = 0; c < 4; c++) s[j][c] = 0.f;

#pragma unroll
        for (int kk = 0; kk < 8; kk++) {
            const int kkc = kk * 16;
            uint32_t ah[4], al[4];
            uint32_t ao = (uint32_t)((wr0 + arow_in) * QSTRD + kkc + acol_add) * 2;
            LDSM4(ah[0], ah[1], ah[2], ah[3], sQh_a + ao);
            LDSM4(al[0], al[1], al[2], al[3], sQl_a + ao);
#pragma unroll
            for (int jp = 0; jp < 4; jp++) {
                uint32_t bo = (uint32_t)((jp * 16 + brow_in) * QSTRD + kkc + bcol_add) * 2;
                uint32_t bh[4];
                LDSM4(bh[0], bh[1], bh[2], bh[3], sK_a + bo);
                mma16816h(s[2*jp],   ah, bh[0], bh[1]);
                mma16816h(s[2*jp],   al, bh[0], bh[1]);
                mma16816h(s[2*jp+1], ah, bh[2], bh[3]);
                mma16816h(s[2*jp+1], al, bh[2], bh[3]);
            }
        }

        // ---- mask (skip fully-causal tiles for this warp) ----
        if (k0 + 63 > q0 + wr0) {
#pragma unroll
            for (int j = 0; j < 8; j++) {
                int c0g = k0 + j * 8 + fc2, c1g = c0g + 1;
                s[j][0] = (c0g <= r0g) ? s[j][0] : 0.f;
                s[j][1] = (c1g <= r0g) ? s[j][1] : 0.f;
                s[j][2] = (c0g <= r1g) ? s[j][2] : 0.f;
                s[j][3] = (c1g <= r1g) ? s[j][3] : 0.f;
            }
        }

        // ---- row max ----
        float rm0 = -1e30f, rm1 = -1e30f;
#pragma unroll
        for (int j = 0; j < 8; j++) {
            rm0 = fmaxf(rm0, fmaxf(s[j][0], s[j][1]));
            rm1 = fmaxf(rm1, fmaxf(s[j][2], s[j][3]));
        }
        rm0 = fmaxf(rm0, __shfl_xor_sync(0xffffffffu, rm0, 1));
        rm0 = fmaxf(rm0, __shfl_xor_sync(0xffffffffu, rm0, 2));
        rm1 = fmaxf(rm1, __shfl_xor_sync(0xffffffffu, rm1, 1));
        rm1 = fmaxf(rm1, __shfl_xor_sync(0xffffffffu, rm1, 2));

        float mn0 = fmaxf(m0, rm0), mn1 = fmaxf(m1, rm1);
        if (mn0 > m0 || mn1 > m1) {
            float f0 = ex2f(m0 - mn0), f1 = ex2f(m1 - mn1);
#pragma unroll
            for (int j = 0; j < 16; j++) {
                o_acc[j][0] *= f0; o_acc[j][1] *= f0;
                o_acc[j][2] *= f1; o_acc[j][3] *= f1;
            }
            l_acc[0] *= f0; l_acc[1] *= f0;
            l_acc[2] *= f1; l_acc[3] *= f1;
            m0 = mn0; m1 = mn1;
        }

        // ---- P = exp2(s - m), fp32 ex2 then pack ----
        uint32_t P0[8], P1[8];
#pragma unroll
        for (int j = 0; j < 8; j++) {
            P0[j] = pkh(ex2f(s[j][0] - m0), ex2f(s[j][1] - m0));
            P1[j] = pkh(ex2f(s[j][2] - m1), ex2f(s[j][3] - m1));
        }

        // ---- P @ V + l (ones-column MMA) ----
#pragma unroll
        for (int kk2 = 0; kk2 < 4; kk2++) {
            uint32_t ph[4] = {P0[2*kk2], P1[2*kk2], P0[2*kk2+1], P1[2*kk2+1]};
            mma16816h(l_acc, ph, ONES, ONES);
#pragma unroll
            for (int jp2 = 0; jp2 < 8; jp2++) {
                uint32_t vo = (uint32_t)((jp2 * 16 + brow_in) * VSTRD + kk2 * 16 + bcol_add) * 2;
                uint32_t vh[4];
                LDSM4(vh[0], vh[1], vh[2], vh[3], sV_a + vo);
                mma16816h(o_acc[2*jp2],   ph, vh[0], vh[1]);
                mma16816h(o_acc[2*jp2+1], ph, vh[2], vh[3]);
            }
        }
        __syncthreads();
    }

    float l0 = l_acc[0], l1 = l_acc[2];

    // ---- analytic masked tail ----
    const int n_tail = S_ - (q0 + 128);
    if (n_tail > 0) {
        const float* suf = g_vsuf + ((size_t)(ntiles * B_ + b) * KVH_ + kvh) * HD_;
        float mn0 = fmaxf(m0, 0.f), mn1 = fmaxf(m1, 0.f);
        float f0 = ex2f(m0 - mn0), f1 = ex2f(m1 - mn1);
        float pt0 = ex2f(0.f - mn0), pt1 = ex2f(0.f - mn1);
        l0 = l0 * f0 + (float)n_tail * pt0;
        l1 = l1 * f1 + (float)n_tail * pt1;
#pragma unroll
        for (int j2 = 0; j2 < 16; j2++) {
            float2 sv = *(const float2*)(suf + j2 * 8 + fc2);
            o_acc[j2][0] = o_acc[j2][0] * f0 + pt0 * sv.x;
            o_acc[j2][1] = o_acc[j2][1] * f0 + pt0 * sv.y;
            o_acc[j2][2] = o_acc[j2][2] * f1 + pt1 * sv.x;
            o_acc[j2][3] = o_acc[j2][3] * f1 + pt1 * sv.y;
        }
    }

    // ---- normalize + write fp16 [b, s, h*128 + d] ----
    const float inv0 = 1.f / l0, inv1 = 1.f / l1;
    const size_t ob0 = (size_t)(b * S_ + r0g) * (H_ * HD_) + h * HD_;
    const size_t ob1 = (size_t)(b * S_ + r1g) * (H_ * HD_) + h * HD_;
#pragma unroll
    for (int j2 = 0; j2 < 16; j2++) {
        int d = j2 * 8 + fc2;
        *(uint32_t*)(O16 + ob0 + d) = pkh(o_acc[j2][0] * inv0, o_acc[j2][1] * inv0);
        *(uint32_t*)(O16 + ob1 + d) = pkh(o_acc[j2][2] * inv1, o_acc[j2][3] * inv1);
    }
}

// ---------------------------------------------------------------------------
// Inputs: 0:x 1:freqs_cos 2:freqs_sin 3:mask 4:wq 5:wk 6:wv 7:wo
//         8:cache_k 9:cache_v 10:start_pos
// ---------------------------------------------------------------------------
extern "C" void kernel_launch(void* const* d_in, const int* in_sizes, int n_in,
                              void* d_out, int out_size) {
    const float* x    = (const float*)d_in[0];
    const float* fcos = (const float*)d_in[1];
    const float* fsin = (const float*)d_in[2];
    const float* wq   = (const float*)d_in[4];
    const float* wk   = (const float*)d_in[5];
    const float* wv   = (const float*)d_in[6];
    const float* wo   = (const float*)d_in[7];
    float* out = (float*)d_out;

    __half *xh, *wqT, *wkT, *wvT, *woT, *ah;
    __half *qch, *qcl, *kch, *vt16;
    cudaGetSymbolAddress((void**)&xh,  g_xh);
    cudaGetSymbolAddress((void**)&wqT, g_wqT);
    cudaGetSymbolAddress((void**)&wkT, g_wkT);
    cudaGetSymbolAddress((void**)&wvT, g_wvT);
    cudaGetSymbolAddress((void**)&woT, g_woT);
    cudaGetSymbolAddress((void**)&ah,  g_ah);
    cudaGetSymbolAddress((void**)&qch, g_qch);
    cudaGetSymbolAddress((void**)&qcl, g_qcl);
    cudaGetSymbolAddress((void**)&kch, g_kch);
    cudaGetSymbolAddress((void**)&vt16, g_vt16);

    const int M = B_ * S_;
    const int NQ = H_ * HD_;
    const int NKV = KVH_ * HD_;

    cudaFuncSetAttribute(gemm_hmma, cudaFuncAttributeMaxDynamicSharedMemorySize,
                         GSMEM_1);
    cudaFuncSetAttribute(gemm_vproj, cudaFuncAttributeMaxDynamicSharedMemorySize,
                         GSMEM_1);
    cudaFuncSetAttribute(gemm_hmma_rope_h, cudaFuncAttributeMaxDynamicSharedMemorySize,
                         GSMEM_1);
    cudaFuncSetAttribute(attn_hmma, cudaFuncAttributeMaxDynamicSharedMemorySize,
                         ATTN_SMEM);

    // 1: activation convert (single fp16; no lo needed anymore)
    {
        int n4 = M * D_ / 4;
        conv_h<<<(n4 + 255) / 256, 256>>>((const float4*)x, xh, n4);
    }
    // 2: all weight transposes in one launch
    transp_all<<<40960, dim3(32, 8)>>>(wq, wk, wv, wo, wqT, wkT, wvT, woT);

    // 3: Q projection — single-A fp16, fused RoPE, fp16 hi/lo out
    gemm_hmma_rope_h<<<dim3(NQ / 128, M / 128), 256, GSMEM_1>>>(
        xh, wqT, qch, qcl, fcos, fsin, H_, 1, SCALE_L2E, M, NQ, D_);
    // 4: K projection — single-A fp16, fused RoPE, single fp16 out
    gemm_hmma_rope_h<<<dim3(NKV / 128, M / 128), 256, GSMEM_1>>>(
        xh, wkT, kch, kch, fcos, fsin, KVH_, 0, 1.0f, M, NKV, D_);
    // 5: V projection — single-A, writes transposed fp16 directly
    gemm_vproj<<<dim3(NKV / 128, M / 128), 256, GSMEM_1>>>(xh, wvT, vt16);

    // 6-7: suffix V sums (from fp16 transposed V)
    vtile_sums<<<dim3(32, B_ * KVH_), 128>>>(vt16);
    vsuffix_scan<<<8, 256>>>();

    // 8: attention
    attn_hmma<<<dim3(H_, S_ / 128, B_), 256, ATTN_SMEM>>>(qch, qcl, kch, vt16, ah);

    // 9: output projection (single-A, output-linear)
    gemm_hmma<<<dim3(D_ / 128, M / 128), 256, GSMEM_1>>>(
        ah, woT, out, M, D_, D_);
}